// round 1
// baseline (speedup 1.0000x reference)
#include <cuda_runtime.h>
#include <math.h>

// ---------------- problem constants ----------------
#define DTH 256            // threads per block
#define HID 64
#define IN_MAIN 51         // 32 feat + 3 vdn + 16 tf
#define IN_MOT  48         // 32 + 16 (temb folded into bias)

// shared layout (float offsets)
#define W1OP   0            // 51*64 = 3264
#define W1COL  3264
#define W1COV  6528
#define W1MOT  9792         // 48*64 = 3072
#define W2OP   12864        // 64*12 (pad 10->12)
#define W2COL  13632        // 64*32 (pad 30->32)
#define W2COV  15680        // 64*72 (pad 70->72)
#define W2MOT  20288        // 64*40 (pad 37->40)
#define B1OP   22848
#define B1COL  22912
#define B1COV  22976
#define BMOT   23040        // folded motion bias (b1 + temb @ mot_w1[48:64])
#define B2OP   23104        // 16
#define B2COL  23120        // 32
#define B2COV  23152        // 72
#define B2MOT  23224        // 40
#define TAF    23264        // 51*256 = 13056
#define HBUF   36320        // 64*256 = 16384
#define SMEM_FLOATS 52704
#define SMEM_BYTES (SMEM_FLOATS * 4)

__device__ __forceinline__ void layer1_run(const float* __restrict__ w1,
                                           const float* __restrict__ b1,
                                           int IN,
                                           const float* __restrict__ tafb,
                                           float* __restrict__ hb,
                                           int tid)
{
    #pragma unroll 1
    for (int jc = 0; jc < 4; jc++) {
        float acc[16];
        #pragma unroll
        for (int k = 0; k < 16; k++) acc[k] = b1[jc * 16 + k];
        #pragma unroll 3
        for (int i = 0; i < IN; i++) {
            float x = tafb[i * DTH + tid];
            const float4* wp = reinterpret_cast<const float4*>(w1 + i * 64 + jc * 16);
            float4 wa = wp[0], wb = wp[1], wc = wp[2], wd = wp[3];
            acc[0]  = fmaf(x, wa.x, acc[0]);  acc[1]  = fmaf(x, wa.y, acc[1]);
            acc[2]  = fmaf(x, wa.z, acc[2]);  acc[3]  = fmaf(x, wa.w, acc[3]);
            acc[4]  = fmaf(x, wb.x, acc[4]);  acc[5]  = fmaf(x, wb.y, acc[5]);
            acc[6]  = fmaf(x, wb.z, acc[6]);  acc[7]  = fmaf(x, wb.w, acc[7]);
            acc[8]  = fmaf(x, wc.x, acc[8]);  acc[9]  = fmaf(x, wc.y, acc[9]);
            acc[10] = fmaf(x, wc.z, acc[10]); acc[11] = fmaf(x, wc.w, acc[11]);
            acc[12] = fmaf(x, wd.x, acc[12]); acc[13] = fmaf(x, wd.y, acc[13]);
            acc[14] = fmaf(x, wd.z, acc[14]); acc[15] = fmaf(x, wd.w, acc[15]);
        }
        #pragma unroll
        for (int k = 0; k < 16; k++)
            hb[(jc * 16 + k) * DTH + tid] = fmaxf(acc[k], 0.f);
    }
}

template <int CHUNK>
__device__ __forceinline__ void layer2_acc(const float* __restrict__ w2, int stride, int k0,
                                           const float* __restrict__ hb, int tid,
                                           float acc[CHUNK])
{
    #pragma unroll 4
    for (int j = 0; j < 64; j++) {
        float hj = hb[j * DTH + tid];
        const float4* wp = reinterpret_cast<const float4*>(w2 + j * stride + k0);
        #pragma unroll
        for (int q = 0; q < CHUNK / 4; q++) {
            float4 w = wp[q];
            acc[4 * q + 0] = fmaf(hj, w.x, acc[4 * q + 0]);
            acc[4 * q + 1] = fmaf(hj, w.y, acc[4 * q + 1]);
            acc[4 * q + 2] = fmaf(hj, w.z, acc[4 * q + 2]);
            acc[4 * q + 3] = fmaf(hj, w.w, acc[4 * q + 3]);
        }
    }
}

__device__ __forceinline__ float sigmoidf_(float x) { return 1.f / (1.f + expf(-x)); }

__global__ __launch_bounds__(DTH)
void gif_eval_kernel(const float* __restrict__ cam,
                     const float* __restrict__ anchors,
                     const float* __restrict__ scales,
                     const float* __restrict__ afeat,
                     const float* __restrict__ tfeat,
                     const float* __restrict__ factors,
                     const float* __restrict__ op_w1, const float* __restrict__ op_b1,
                     const float* __restrict__ op_w2, const float* __restrict__ op_b2,
                     const float* __restrict__ col_w1, const float* __restrict__ col_b1,
                     const float* __restrict__ col_w2, const float* __restrict__ col_b2,
                     const float* __restrict__ cov_w1, const float* __restrict__ cov_b1,
                     const float* __restrict__ cov_w2, const float* __restrict__ cov_b2,
                     const float* __restrict__ mot_w1, const float* __restrict__ mot_b1,
                     const float* __restrict__ mot_w2, const float* __restrict__ mot_b2,
                     const int* __restrict__ vis,
                     const int* __restrict__ knn,
                     float* __restrict__ out,
                     int M)
{
    extern __shared__ float S[];
    const int tid = threadIdx.x;

    // ---- stage weights into shared ----
    for (int i = tid; i < 3264; i += DTH) {
        S[W1OP  + i] = op_w1[i];
        S[W1COL + i] = col_w1[i];
        S[W1COV + i] = cov_w1[i];
    }
    for (int i = tid; i < 3072; i += DTH) S[W1MOT + i] = mot_w1[i];  // rows 0..47
    for (int i = tid; i < 768; i += DTH) {
        int j = i / 12, k = i - j * 12;
        S[W2OP + i] = (k < 10) ? op_w2[j * 10 + k] : 0.f;
    }
    for (int i = tid; i < 2048; i += DTH) {
        int j = i >> 5, k = i & 31;
        S[W2COL + i] = (k < 30) ? col_w2[j * 30 + k] : 0.f;
    }
    for (int i = tid; i < 4608; i += DTH) {
        int j = i / 72, k = i - j * 72;
        S[W2COV + i] = (k < 70) ? cov_w2[j * 70 + k] : 0.f;
    }
    for (int i = tid; i < 2560; i += DTH) {
        int j = i / 40, k = i - j * 40;
        S[W2MOT + i] = (k < 37) ? mot_w2[j * 37 + k] : 0.f;
    }
    if (tid < 64) {
        S[B1OP  + tid] = op_b1[tid];
        S[B1COL + tid] = col_b1[tid];
        S[B1COV + tid] = cov_b1[tid];
        // fold temb (constant) into motion layer-1 bias
        float acc = mot_b1[tid];
        #pragma unroll
        for (int t = 0; t < 8; t++) {
            float ang = exp2f((float)t) * 1.5707963267948966f;   // 2^t * pi * 0.5
            acc = fmaf(sinf(ang), mot_w1[(48 + t) * 64 + tid], acc);
            acc = fmaf(cosf(ang), mot_w1[(56 + t) * 64 + tid], acc);
        }
        S[BMOT + tid] = acc;
    }
    if (tid < 16) S[B2OP  + tid] = (tid < 10) ? op_b2[tid]  : 0.f;
    if (tid < 32) S[B2COL + tid] = (tid < 30) ? col_b2[tid] : 0.f;
    if (tid < 72) S[B2COV + tid] = (tid < 70) ? cov_b2[tid] : 0.f;
    if (tid < 40) S[B2MOT + tid] = (tid < 37) ? mot_b2[tid] : 0.f;
    __syncthreads();

    const int m = blockIdx.x * DTH + tid;
    if (m >= M) return;

    const int idx = vis[m];

    // ---- build taf in shared: [feat(32), vdn(3), tf*tff(16)] ----
    const float4* fp = reinterpret_cast<const float4*>(afeat + (long long)idx * 32);
    #pragma unroll
    for (int q = 0; q < 8; q++) {
        float4 v = __ldg(fp + q);
        S[TAF + (4 * q + 0) * DTH + tid] = v.x;
        S[TAF + (4 * q + 1) * DTH + tid] = v.y;
        S[TAF + (4 * q + 2) * DTH + tid] = v.z;
        S[TAF + (4 * q + 3) * DTH + tid] = v.w;
    }
    float ax = __ldg(anchors + (long long)idx * 3 + 0);
    float ay = __ldg(anchors + (long long)idx * 3 + 1);
    float az = __ldg(anchors + (long long)idx * 3 + 2);
    float vx = ax - cam[3], vy = ay - cam[7], vz = az - cam[11];
    float nrm = sqrtf(vx * vx + vy * vy + vz * vz);
    float inv = 1.f / fmaxf(nrm, 1e-8f);
    S[TAF + 32 * DTH + tid] = vx * inv;
    S[TAF + 33 * DTH + tid] = vy * inv;
    S[TAF + 34 * DTH + tid] = vz * inv;

    float4 fc = __ldg(reinterpret_cast<const float4*>(factors + (long long)idx * 4));
    float tff = fc.x, mf = fc.y, kf = fc.z, pf = fc.w;

    const float4* tp = reinterpret_cast<const float4*>(tfeat + (long long)idx * 256 + 112);
    #pragma unroll
    for (int q = 0; q < 4; q++) {
        float4 v = __ldg(tp + q);
        S[TAF + (35 + 4 * q + 0) * DTH + tid] = v.x * tff;
        S[TAF + (35 + 4 * q + 1) * DTH + tid] = v.y * tff;
        S[TAF + (35 + 4 * q + 2) * DTH + tid] = v.z * tff;
        S[TAF + (35 + 4 * q + 3) * DTH + tid] = v.w * tff;
    }

    float* omk = out + (long long)m * 110;

    // ---- opacity MLP (51->64->10, tanh, *pf) ----
    {
        layer1_run(S + W1OP, S + B1OP, IN_MAIN, S + TAF, S + HBUF, tid);
        float acc[12];
        #pragma unroll
        for (int k = 0; k < 12; k++) acc[k] = S[B2OP + k];
        layer2_acc<12>(S + W2OP, 12, 0, S + HBUF, tid, acc);
        #pragma unroll
        for (int k = 0; k < 10; k++)
            omk[k * 11] = tanhf(acc[k]) * pf;
    }

    // ---- color MLP (51->64->30, sigmoid) ----
    {
        layer1_run(S + W1COL, S + B1COL, IN_MAIN, S + TAF, S + HBUF, tid);
        #pragma unroll 1
        for (int p = 0; p < 2; p++) {
            int k0 = p * 16;
            float acc[16];
            #pragma unroll
            for (int k = 0; k < 16; k++) acc[k] = S[B2COL + k0 + k];
            layer2_acc<16>(S + W2COL, 32, k0, S + HBUF, tid, acc);
            #pragma unroll
            for (int kk = 0; kk < 16; kk++) {
                int k = k0 + kk;
                if (k < 30) {
                    int kd = k / 3;
                    omk[kd * 11 + 1 + (k - kd * 3)] = sigmoidf_(acc[kk]);
                }
            }
        }
    }

    // ---- cov MLP (51->64->70, raw) ----
    {
        layer1_run(S + W1COV, S + B1COV, IN_MAIN, S + TAF, S + HBUF, tid);
        #pragma unroll 1
        for (int p = 0; p < 6; p++) {
            int k0 = p * 12;
            float acc[12];
            #pragma unroll
            for (int k = 0; k < 12; k++) acc[k] = S[B2COV + k0 + k];
            layer2_acc<12>(S + W2COV, 72, k0, S + HBUF, tid, acc);
            #pragma unroll
            for (int kk = 0; kk < 12; kk++) {
                int k = k0 + kk;
                if (k < 70) {
                    int kd = k / 7;
                    omk[kd * 11 + 4 + (k - kd * 7)] = acc[kk];
                }
            }
        }
    }

    // ---- build taf_ in shared (48 dims), temb folded into bias ----
    {
        float facc[48];
        #pragma unroll
        for (int i = 0; i < 48; i++) facc[i] = 0.f;
        const int* kp = knn + (long long)idx * 6;
        #pragma unroll 1
        for (int nb = 0; nb < 6; nb++) {
            int nidx = __ldg(kp + nb);
            const float4* nf = reinterpret_cast<const float4*>(afeat + (long long)nidx * 32);
            #pragma unroll
            for (int q = 0; q < 8; q++) {
                float4 v = __ldg(nf + q);
                facc[4 * q + 0] += v.x; facc[4 * q + 1] += v.y;
                facc[4 * q + 2] += v.z; facc[4 * q + 3] += v.w;
            }
            const float4* nt = reinterpret_cast<const float4*>(tfeat + (long long)nidx * 256 + 112);
            #pragma unroll
            for (int q = 0; q < 4; q++) {
                float4 v = __ldg(nt + q);
                facc[32 + 4 * q + 0] += v.x; facc[32 + 4 * q + 1] += v.y;
                facc[32 + 4 * q + 2] += v.z; facc[32 + 4 * q + 3] += v.w;
            }
        }
        float wk = (1.f - kf) * (1.f / 6.f);
        #pragma unroll
        for (int i = 0; i < 32; i++)
            S[TAF + i * DTH + tid] = kf * S[TAF + i * DTH + tid] + wk * facc[i];
        #pragma unroll
        for (int c = 0; c < 16; c++)
            S[TAF + (32 + c) * DTH + tid] = kf * S[TAF + (35 + c) * DTH + tid] + wk * facc[32 + c];
    }

    float* om = out + (long long)M * 110 + (long long)m * 50;

    // ---- motion MLP (48->64->37, *mf) ----
    {
        layer1_run(S + W1MOT, S + BMOT, IN_MOT, S + TAF, S + HBUF, tid);
        #pragma unroll 1
        for (int p = 0; p < 2; p++) {
            int k0 = p * 20;
            float acc[20];
            #pragma unroll
            for (int k = 0; k < 20; k++) acc[k] = S[B2MOT + k0 + k];
            layer2_acc<20>(S + W2MOT, 40, k0, S + HBUF, tid, acc);
            #pragma unroll
            for (int kk = 0; kk < 20; kk++) {
                int k = k0 + kk;
                if (k < 37) om[k] = acc[kk] * mf;
            }
        }
    }

    // ---- epilogue: scales(exp, last3*pf), factors, anchor ----
    {
        const float* sp = scales + (long long)idx * 6;
        om[37] = expf(__ldg(sp + 0));
        om[38] = expf(__ldg(sp + 1));
        om[39] = expf(__ldg(sp + 2));
        om[40] = expf(__ldg(sp + 3)) * pf;
        om[41] = expf(__ldg(sp + 4)) * pf;
        om[42] = expf(__ldg(sp + 5)) * pf;
        om[43] = tff; om[44] = mf; om[45] = kf; om[46] = pf;
        om[47] = ax; om[48] = ay; om[49] = az;
    }
}

extern "C" void kernel_launch(void* const* d_in, const int* in_sizes, int n_in,
                              void* d_out, int out_size)
{
    const float* cam     = (const float*)d_in[0];
    const float* anchors = (const float*)d_in[1];
    const float* scales  = (const float*)d_in[2];
    const float* afeat   = (const float*)d_in[3];
    const float* tfeat   = (const float*)d_in[4];
    const float* factors = (const float*)d_in[5];
    const float* op_w1   = (const float*)d_in[6];
    const float* op_b1   = (const float*)d_in[7];
    const float* op_w2   = (const float*)d_in[8];
    const float* op_b2   = (const float*)d_in[9];
    const float* col_w1  = (const float*)d_in[10];
    const float* col_b1  = (const float*)d_in[11];
    const float* col_w2  = (const float*)d_in[12];
    const float* col_b2  = (const float*)d_in[13];
    const float* cov_w1  = (const float*)d_in[14];
    const float* cov_b1  = (const float*)d_in[15];
    const float* cov_w2  = (const float*)d_in[16];
    const float* cov_b2  = (const float*)d_in[17];
    const float* mot_w1  = (const float*)d_in[18];
    const float* mot_b1  = (const float*)d_in[19];
    const float* mot_w2  = (const float*)d_in[20];
    const float* mot_b2  = (const float*)d_in[21];
    const int*   vis     = (const int*)d_in[22];
    const int*   knn     = (const int*)d_in[23];

    int M = in_sizes[22];
    float* out = (float*)d_out;

    cudaFuncSetAttribute(gif_eval_kernel,
                         cudaFuncAttributeMaxDynamicSharedMemorySize, SMEM_BYTES);

    int grid = (M + DTH - 1) / DTH;
    gif_eval_kernel<<<grid, DTH, SMEM_BYTES>>>(
        cam, anchors, scales, afeat, tfeat, factors,
        op_w1, op_b1, op_w2, op_b2,
        col_w1, col_b1, col_w2, col_b2,
        cov_w1, cov_b1, cov_w2, cov_b2,
        mot_w1, mot_b1, mot_w2, mot_b2,
        vis, knn, out, M);
}